// round 14
// baseline (speedup 1.0000x reference)
#include <cuda_runtime.h>
#include <cstdint>

#define NN 100000
#define EE 800000
#define GG 64
#define HH 128
#define FIN 64
#define NBLK ((NN + 1023) / 1024)   // 98
#define S1 50048                    // split point (multiple of 64 and 16)

// Scratch (__device__ globals; no allocation allowed)
__device__ __align__(16) float g_u[(size_t)NN * HH];
__device__ __align__(16) float g_za[(size_t)NN * HH];
__device__ __align__(16) float g_zb[(size_t)NN * HH];
__device__ float g_dinv[NN];
__device__ int   g_cnt[NN];
__device__ int   g_off[NN + 1];
__device__ int   g_cur[NN];
__device__ int   g_csr[EE];
__device__ int   g_bsum[128];

// ---------------------------------------------------------------------------
__device__ __forceinline__ void ffma2(unsigned long long& acc, unsigned long long a,
                                      unsigned long long b) {
    asm("fma.rn.f32x2 %0, %1, %2, %0;" : "+l"(acc) : "l"(a), "l"(b));
}
__device__ __forceinline__ float fsum2(unsigned long long v) {
    float lo, hi;
    asm("mov.b64 {%0,%1}, %2;" : "=f"(lo), "=f"(hi) : "l"(v));
    return lo + hi;
}

// ---------------------------------------------------------------------------
__global__ void init_kernel() {
    int i = blockIdx.x * blockDim.x + threadIdx.x;
    if (i < NN) g_cnt[i] = 0;
}
__global__ void hist_kernel(const int* __restrict__ ei) {
    int e = blockIdx.x * blockDim.x + threadIdx.x;
    if (e < EE) atomicAdd(&g_cnt[ei[EE + e]], 1);
}

// Block scan (1024/block) + dinv
__global__ void scan1_kernel() {
    __shared__ int ssum[256];
    const int tid = threadIdx.x;
    const int base = blockIdx.x * 1024 + tid * 4;
    int v[4];
#pragma unroll
    for (int j = 0; j < 4; j++) {
        int idx = base + j;
        v[j] = (idx < NN) ? g_cnt[idx] : 0;
        if (idx < NN) g_dinv[idx] = rsqrtf((float)v[j] + 1.0f);
    }
    int s = v[0] + v[1] + v[2] + v[3];
    ssum[tid] = s;
    __syncthreads();
    for (int d = 1; d < 256; d <<= 1) {
        int t = (tid >= d) ? ssum[tid - d] : 0;
        __syncthreads();
        ssum[tid] += t;
        __syncthreads();
    }
    int run = ssum[tid] - s;
#pragma unroll
    for (int j = 0; j < 4; j++) {
        int idx = base + j;
        if (idx < NN) g_off[idx] = run;
        run += v[j];
    }
    if (tid == 255) g_bsum[blockIdx.x] = ssum[255];
}

// scan3: scan2 folded in (each block redundantly scans the 98 block sums).
__global__ void scan3_kernel() {
    __shared__ int pre[128];
    const int tid = threadIdx.x;  // 256
    int v = 0;
    if (tid < 128) {
        v = (tid < NBLK) ? g_bsum[tid] : 0;
        pre[tid] = v;
    }
    __syncthreads();
    for (int d = 1; d < 128; d <<= 1) {
        int t = 0;
        if (tid < 128 && tid >= d) t = pre[tid - d];
        __syncthreads();
        if (tid < 128) pre[tid] += t;
        __syncthreads();
    }
    if (tid < 128) pre[tid] -= v;  // exclusive
    __syncthreads();
    int i = blockIdx.x * 256 + tid;
    if (i < NN) {
        int off = g_off[i] + pre[i >> 10];
        g_off[i] = off;
        g_cur[i] = off;
    }
    if (i == 0) g_off[NN] = EE;
}
__global__ void scatter_kernel(const int* __restrict__ ei) {
    int e = blockIdx.x * blockDim.x + threadIdx.x;
    if (e >= EE) return;
    int pos = atomicAdd(&g_cur[ei[EE + e]], 1);
    g_csr[pos] = ei[e];
}

// ---------------------------------------------------------------------------
// Aggregation u = A_hat * z over node range [nodeBase, nodeEnd).
template <int DIM>
__global__ void agg_kernel(const float* __restrict__ z, float* __restrict__ u,
                           int nodeBase, int nodeEnd) {
    constexpr int GPN = DIM / 4;
    constexpr int SH = (DIM == 64) ? 4 : 5;
    const int gt = blockIdx.x * 256 + threadIdx.x;
    const int node = nodeBase + (gt >> SH);
    if (node >= nodeEnd) return;
    const int q = gt & (GPN - 1);
    const float dd = g_dinv[node];
    const int s = g_off[node], e = g_off[node + 1];
    const float4* Z = (const float4*)z;
    float4 v0 = Z[(size_t)node * GPN + q];
    float ax = dd * v0.x, ay = dd * v0.y, az = dd * v0.z, aw = dd * v0.w;
    int i = s;
    for (; i + 4 <= e; i += 4) {
        int s0 = g_csr[i], s1 = g_csr[i + 1], s2 = g_csr[i + 2], s3 = g_csr[i + 3];
        float d0 = g_dinv[s0], d1 = g_dinv[s1], d2 = g_dinv[s2], d3 = g_dinv[s3];
        float4 a = Z[(size_t)s0 * GPN + q];
        float4 b = Z[(size_t)s1 * GPN + q];
        float4 c = Z[(size_t)s2 * GPN + q];
        float4 d4 = Z[(size_t)s3 * GPN + q];
        ax += d0 * a.x + d1 * b.x + d2 * c.x + d3 * d4.x;
        ay += d0 * a.y + d1 * b.y + d2 * c.y + d3 * d4.y;
        az += d0 * a.z + d1 * b.z + d2 * c.z + d3 * d4.z;
        aw += d0 * a.w + d1 * b.w + d2 * c.w + d3 * d4.w;
    }
    for (; i < e; i++) {
        int s0 = g_csr[i];
        float d0 = g_dinv[s0];
        float4 a = Z[(size_t)s0 * GPN + q];
        ax += d0 * a.x; ay += d0 * a.y; az += d0 * a.z; aw += d0 * a.w;
    }
    ((float4*)u)[(size_t)node * GPN + q] = make_float4(dd * ax, dd * ay, dd * az, dd * aw);
}

// ---------------------------------------------------------------------------
// FFMA2 GEMM over row range starting at rowBase:
// Z[rows,128] = relu(A[rows,K] @ W[K,128] + b).
template <int K>
__global__ void __launch_bounds__(256) gemm_kernel(const float* __restrict__ A,
                                                   const float* __restrict__ W,
                                                   const float* __restrict__ bias,
                                                   float* __restrict__ Z,
                                                   int rowBase) {
    constexpr int KP = K + 4;
    extern __shared__ char smraw[];
    float* Ash = (float*)smraw;                       // [64][KP]
    float2* Wsh = (float2*)(smraw + 64 * KP * 4);     // [128 cols][17 k-pairs]
    const int tid = threadIdx.x;
    const int lane = tid & 31;
    const int rg = tid >> 5;
    const int blockRow = rowBase + blockIdx.x * 64;

#pragma unroll
    for (int f4 = tid; f4 < 64 * (K / 4); f4 += 256) {
        int row = f4 / (K / 4);
        int q = f4 % (K / 4);
        int grow = blockRow + row;
        float4 v = (grow < NN) ? *(const float4*)(A + (size_t)grow * K + q * 4)
                               : make_float4(0.f, 0.f, 0.f, 0.f);
        *(float4*)(Ash + row * KP + 4 * q) = v;
    }

    unsigned long long acc2[8][4];
#pragma unroll
    for (int i = 0; i < 8; i++)
#pragma unroll
        for (int j = 0; j < 4; j++) acc2[i][j] = 0ull;

    for (int kc = 0; kc < K; kc += 32) {
        __syncthreads();
        {
            int c = tid & 127;
            int half = tid >> 7;
#pragma unroll
            for (int t = 0; t < 8; t++) {
                int k2 = half * 8 + t;
                float w0 = W[(size_t)(kc + 2 * k2) * HH + c];
                float w1 = W[(size_t)(kc + 2 * k2 + 1) * HH + c];
                Wsh[c * 17 + k2] = make_float2(w0, w1);
            }
        }
        __syncthreads();
#pragma unroll
        for (int k2 = 0; k2 < 16; k2++) {
            unsigned long long a2[8], w2[4];
#pragma unroll
            for (int i = 0; i < 8; i++)
                a2[i] = *(const unsigned long long*)(Ash + (rg * 8 + i) * KP + kc + 2 * k2);
#pragma unroll
            for (int j = 0; j < 4; j++)
                w2[j] = *(const unsigned long long*)(&Wsh[(lane + 32 * j) * 17 + k2]);
#pragma unroll
            for (int i = 0; i < 8; i++)
#pragma unroll
                for (int j = 0; j < 4; j++) ffma2(acc2[i][j], a2[i], w2[j]);
        }
    }

    float b[4];
#pragma unroll
    for (int j = 0; j < 4; j++) b[j] = bias[lane + 32 * j];
#pragma unroll
    for (int i = 0; i < 8; i++) {
        int grow = blockRow + rg * 8 + i;
        if (grow >= NN) continue;
        float* Zr = Z + (size_t)grow * HH;
#pragma unroll
        for (int j = 0; j < 4; j++) {
            float o = fsum2(acc2[i][j]) + b[j];
            Zr[lane + 32 * j] = fmaxf(o, 0.f);
        }
    }
}

// ---------------------------------------------------------------------------
// Pool + MLP head (layer-3 GEMM folded in by linearity).
__global__ void pool_mlp_kernel(const int* __restrict__ bat,
                                const float* __restrict__ u3,
                                const float* __restrict__ W3,
                                const float* __restrict__ b3,
                                const float* __restrict__ fw1, const float* __restrict__ fb1,
                                const float* __restrict__ fw2, const float* __restrict__ fb2,
                                float* __restrict__ out) {
    const int g = blockIdx.x;
    const int tid = threadIdx.x;  // 256
    __shared__ int bounds[2];
    __shared__ __align__(16) float partial[8 * HH];
    __shared__ __align__(16) float S[HH];
    __shared__ __align__(16) float p[HH];
    __shared__ __align__(16) float z[HH];

    if (tid < 2) {
        int key = g + tid;
        int lo = 0, hi = NN;
        while (lo < hi) {
            int mid = (lo + hi) >> 1;
            if (bat[mid] < key) lo = mid + 1;
            else hi = mid;
        }
        bounds[tid] = lo;
    }
    __syncthreads();
    const int lo = bounds[0], hi = bounds[1];

    {
        const int q = tid & 31;
        const int strip = tid >> 5;
        float4 s = make_float4(0.f, 0.f, 0.f, 0.f);
        const float4* U = (const float4*)u3;
        for (int r = lo + strip; r < hi; r += 8) {
            float4 v = U[(size_t)r * 32 + q];
            s.x += v.x; s.y += v.y; s.z += v.z; s.w += v.w;
        }
        ((float4*)partial)[strip * 32 + q] = s;
    }
    __syncthreads();
    if (tid < HH) {
        float v = 0.f;
#pragma unroll
        for (int st = 0; st < 8; st++) v += partial[st * HH + tid];
        S[tid] = v;
    }
    __syncthreads();

    if (tid < HH) {
        const int j = tid;
        float acc = 0.f;
#pragma unroll 8
        for (int k = 0; k < HH; k++) acc += S[k] * W3[k * HH + j];
        p[j] = (hi > lo) ? acc / (float)(hi - lo) + b3[j] : 0.0f;
    }
    __syncthreads();
    if (tid < HH) {
        const int j = tid;
        float acc = fb1[j];
#pragma unroll 8
        for (int k = 0; k < HH; k++) acc += p[k] * fw1[k * HH + j];
        z[j] = fmaxf(acc, 0.0f);
    }
    __syncthreads();
    if (tid < 4) {
        float o = fb2[tid];
#pragma unroll 8
        for (int k = 0; k < HH; k++) o += z[k] * fw2[k * 4 + tid];
        out[g * 4 + tid] = o;
    }
}

// ---------------------------------------------------------------------------
extern "C" void kernel_launch(void* const* d_in, const int* in_sizes, int n_in,
                              void* d_out, int out_size) {
    const float* x   = (const float*)d_in[0];
    const float* W1  = (const float*)d_in[1];
    const float* b1  = (const float*)d_in[2];
    const float* W2  = (const float*)d_in[3];
    const float* b2  = (const float*)d_in[4];
    const float* W3  = (const float*)d_in[5];
    const float* b3  = (const float*)d_in[6];
    const float* fw1 = (const float*)d_in[7];
    const float* fb1 = (const float*)d_in[8];
    const float* fw2 = (const float*)d_in[9];
    const float* fb2 = (const float*)d_in[10];
    const int*   ei  = (const int*)d_in[11];
    const int*   bat = (const int*)d_in[12];
    float* out = (float*)d_out;

    float *du, *dza, *dzb;
    cudaGetSymbolAddress((void**)&du, g_u);
    cudaGetSymbolAddress((void**)&dza, g_za);
    cudaGetSymbolAddress((void**)&dzb, g_zb);

    const int SMEM64 = 64 * (FIN + 4) * 4 + 128 * 17 * 8;   // 34816
    const int SMEM128 = 64 * (HH + 4) * 4 + 128 * 17 * 8;   // 51200
    cudaFuncSetAttribute(gemm_kernel<FIN>,
                         cudaFuncAttributeMaxDynamicSharedMemorySize, SMEM64);
    cudaFuncSetAttribute(gemm_kernel<HH>,
                         cudaFuncAttributeMaxDynamicSharedMemorySize, SMEM128);

    // Side stream + events for intra-layer overlap (host objects; no device mem)
    cudaStream_t s1;
    cudaStreamCreateWithFlags(&s1, cudaStreamNonBlocking);
    cudaEvent_t ef1, ej1, ef2, ej2;
    cudaEventCreateWithFlags(&ef1, cudaEventDisableTiming);
    cudaEventCreateWithFlags(&ej1, cudaEventDisableTiming);
    cudaEventCreateWithFlags(&ef2, cudaEventDisableTiming);
    cudaEventCreateWithFlags(&ej2, cudaEventDisableTiming);

    // --- CSR build (+ dinv), main stream ---
    init_kernel<<<(NN + 255) / 256, 256>>>();
    hist_kernel<<<(EE + 255) / 256, 256>>>(ei);
    scan1_kernel<<<NBLK, 256>>>();
    scan3_kernel<<<(NN + 255) / 256, 256>>>();
    scatter_kernel<<<(EE + 255) / 256, 256>>>(ei);

    const int AGG1_A = S1 / 16,            AGG1_B = (NN - S1 + 15) / 16;
    const int AGG2_A = S1 / 8,             AGG2_B = (NN - S1 + 7) / 8;
    const int GEMM_A = S1 / 64,            GEMM_B = (NN - S1 + 63) / 64;

    // --- Layer 1 (pipelined halves): u1 = A_hat x ; z1 = relu(u1 W1 + b1) ---
    agg_kernel<FIN><<<AGG1_A, 256>>>(x, du, 0, S1);
    cudaEventRecord(ef1, 0);
    cudaStreamWaitEvent(s1, ef1, 0);
    gemm_kernel<FIN><<<GEMM_A, 256, SMEM64, s1>>>(du, W1, b1, dza, 0);
    agg_kernel<FIN><<<AGG1_B, 256>>>(x, du, S1, NN);
    gemm_kernel<FIN><<<GEMM_B, 256, SMEM64>>>(du, W1, b1, dza, S1);
    cudaEventRecord(ej1, s1);
    cudaStreamWaitEvent(0, ej1, 0);

    // --- Layer 2 (pipelined halves): z2 -> dzb (ping-pong; dza still read) ---
    agg_kernel<HH><<<AGG2_A, 256>>>(dza, du, 0, S1);
    cudaEventRecord(ef2, 0);
    cudaStreamWaitEvent(s1, ef2, 0);
    gemm_kernel<HH><<<GEMM_A, 256, SMEM128, s1>>>(du, W2, b2, dzb, 0);
    agg_kernel<HH><<<AGG2_B, 256>>>(dza, du, S1, NN);
    gemm_kernel<HH><<<GEMM_B, 256, SMEM128>>>(du, W2, b2, dzb, S1);
    cudaEventRecord(ej2, s1);
    cudaStreamWaitEvent(0, ej2, 0);

    // --- Layer 3: aggregation only (GEMM folded into pool_mlp) ---
    agg_kernel<HH><<<(NN * 32 + 255) / 256, 256>>>(dzb, du, 0, NN);

    pool_mlp_kernel<<<GG, 256>>>(bat, du, W3, b3, fw1, fb1, fw2, fb2, out);
}

// round 15
// speedup vs baseline: 1.1896x; 1.1896x over previous
#include <cuda_runtime.h>
#include <cstdint>

#define NN 100000
#define EE 800000
#define GG 64
#define HH 128
#define FIN 64
#define NBLK ((NN + 1023) / 1024)   // 98

// Scratch (__device__ globals; no allocation allowed)
__device__ __align__(16) float g_u[(size_t)NN * HH];
__device__ __align__(16) float g_z[(size_t)NN * HH];
__device__ float g_dinv[NN];
__device__ int   g_cnt[NN];
__device__ int   g_off[NN + 1];
__device__ int   g_cur[NN];
__device__ int   g_csr[EE];
__device__ int   g_bsum[128];
__device__ __align__(16) float g_S[GG * HH];   // per-graph pooled sums

// ---------------------------------------------------------------------------
__device__ __forceinline__ void ffma2(unsigned long long& acc, unsigned long long a,
                                      unsigned long long b) {
    asm("fma.rn.f32x2 %0, %1, %2, %0;" : "+l"(acc) : "l"(a), "l"(b));
}
__device__ __forceinline__ float fsum2(unsigned long long v) {
    float lo, hi;
    asm("mov.b64 {%0,%1}, %2;" : "=f"(lo), "=f"(hi) : "l"(v));
    return lo + hi;
}
__device__ __forceinline__ void redv4(float* p, float4 v) {
    asm volatile("red.global.add.v4.f32 [%0], {%1, %2, %3, %4};" ::"l"(p),
                 "f"(v.x), "f"(v.y), "f"(v.z), "f"(v.w) : "memory");
}

// ---------------------------------------------------------------------------
__global__ void init_kernel() {
    int i = blockIdx.x * blockDim.x + threadIdx.x;
    if (i < NN) g_cnt[i] = 0;
    if (i < GG * HH) g_S[i] = 0.0f;
}
__global__ void hist_kernel(const int* __restrict__ ei) {
    int e = blockIdx.x * blockDim.x + threadIdx.x;
    if (e < EE) atomicAdd(&g_cnt[ei[EE + e]], 1);
}

// Block scan (1024/block) + dinv
__global__ void scan1_kernel() {
    __shared__ int ssum[256];
    const int tid = threadIdx.x;
    const int base = blockIdx.x * 1024 + tid * 4;
    int v[4];
#pragma unroll
    for (int j = 0; j < 4; j++) {
        int idx = base + j;
        v[j] = (idx < NN) ? g_cnt[idx] : 0;
        if (idx < NN) g_dinv[idx] = rsqrtf((float)v[j] + 1.0f);
    }
    int s = v[0] + v[1] + v[2] + v[3];
    ssum[tid] = s;
    __syncthreads();
    for (int d = 1; d < 256; d <<= 1) {
        int t = (tid >= d) ? ssum[tid - d] : 0;
        __syncthreads();
        ssum[tid] += t;
        __syncthreads();
    }
    int run = ssum[tid] - s;
#pragma unroll
    for (int j = 0; j < 4; j++) {
        int idx = base + j;
        if (idx < NN) g_off[idx] = run;
        run += v[j];
    }
    if (tid == 255) g_bsum[blockIdx.x] = ssum[255];
}

// scan3: scan2 folded in (each block redundantly scans the 98 block sums).
__global__ void scan3_kernel() {
    __shared__ int pre[128];
    const int tid = threadIdx.x;  // 256
    int v = 0;
    if (tid < 128) {
        v = (tid < NBLK) ? g_bsum[tid] : 0;
        pre[tid] = v;
    }
    __syncthreads();
    for (int d = 1; d < 128; d <<= 1) {
        int t = 0;
        if (tid < 128 && tid >= d) t = pre[tid - d];
        __syncthreads();
        if (tid < 128) pre[tid] += t;
        __syncthreads();
    }
    if (tid < 128) pre[tid] -= v;  // exclusive
    __syncthreads();
    int i = blockIdx.x * 256 + tid;
    if (i < NN) {
        int off = g_off[i] + pre[i >> 10];
        g_off[i] = off;
        g_cur[i] = off;
    }
    if (i == 0) g_off[NN] = EE;
}
__global__ void scatter_kernel(const int* __restrict__ ei) {
    int e = blockIdx.x * blockDim.x + threadIdx.x;
    if (e >= EE) return;
    int pos = atomicAdd(&g_cur[ei[EE + e]], 1);
    g_csr[pos] = ei[e];
}

// ---------------------------------------------------------------------------
// Aggregation u = A_hat * z (CSR, atomic-free). Unroll-4, batched prefetch.
template <int DIM>
__global__ void agg_kernel(const float* __restrict__ z, float* __restrict__ u) {
    constexpr int GPN = DIM / 4;
    constexpr int SH = (DIM == 64) ? 4 : 5;
    const int gt = blockIdx.x * 256 + threadIdx.x;
    const int node = gt >> SH;
    if (node >= NN) return;
    const int q = gt & (GPN - 1);
    const float dd = g_dinv[node];
    const int s = g_off[node], e = g_off[node + 1];
    const float4* Z = (const float4*)z;
    float4 v0 = Z[(size_t)node * GPN + q];
    float ax = dd * v0.x, ay = dd * v0.y, az = dd * v0.z, aw = dd * v0.w;
    int i = s;
    for (; i + 4 <= e; i += 4) {
        int s0 = g_csr[i], s1 = g_csr[i + 1], s2 = g_csr[i + 2], s3 = g_csr[i + 3];
        float d0 = g_dinv[s0], d1 = g_dinv[s1], d2 = g_dinv[s2], d3 = g_dinv[s3];
        float4 a = Z[(size_t)s0 * GPN + q];
        float4 b = Z[(size_t)s1 * GPN + q];
        float4 c = Z[(size_t)s2 * GPN + q];
        float4 d4 = Z[(size_t)s3 * GPN + q];
        ax += d0 * a.x + d1 * b.x + d2 * c.x + d3 * d4.x;
        ay += d0 * a.y + d1 * b.y + d2 * c.y + d3 * d4.y;
        az += d0 * a.z + d1 * b.z + d2 * c.z + d3 * d4.z;
        aw += d0 * a.w + d1 * b.w + d2 * c.w + d3 * d4.w;
    }
    for (; i < e; i++) {
        int s0 = g_csr[i];
        float d0 = g_dinv[s0];
        float4 a = Z[(size_t)s0 * GPN + q];
        ax += d0 * a.x; ay += d0 * a.y; az += d0 * a.z; aw += d0 * a.w;
    }
    ((float4*)u)[(size_t)node * GPN + q] = make_float4(dd * ax, dd * ay, dd * az, dd * aw);
}

// ---------------------------------------------------------------------------
// Layer-3 aggregation fused with pooling: computes u3 rows in registers and
// reduces them straight into g_S[graph] (no u3 materialization).
// 256 threads = 8 nodes/block (GPN=32). Graph-uniform fast path.
__global__ void agg3_pool_kernel(const float* __restrict__ z,
                                 const int* __restrict__ bat) {
    __shared__ __align__(16) float part[8][HH];
    __shared__ int sg[8];
    const int gt = blockIdx.x * 256 + threadIdx.x;
    const int node = gt >> 5;            // exact: NN*32 == grid*256
    const int q = threadIdx.x & 31;
    const int nl = threadIdx.x >> 5;     // node-local 0..7
    const float dd = g_dinv[node];
    const int s = g_off[node], e = g_off[node + 1];
    const float4* Z = (const float4*)z;
    float4 v0 = Z[(size_t)node * 32 + q];
    float ax = dd * v0.x, ay = dd * v0.y, az = dd * v0.z, aw = dd * v0.w;
    int i = s;
    for (; i + 4 <= e; i += 4) {
        int s0 = g_csr[i], s1 = g_csr[i + 1], s2 = g_csr[i + 2], s3 = g_csr[i + 3];
        float d0 = g_dinv[s0], d1 = g_dinv[s1], d2 = g_dinv[s2], d3 = g_dinv[s3];
        float4 a = Z[(size_t)s0 * 32 + q];
        float4 b = Z[(size_t)s1 * 32 + q];
        float4 c = Z[(size_t)s2 * 32 + q];
        float4 d4 = Z[(size_t)s3 * 32 + q];
        ax += d0 * a.x + d1 * b.x + d2 * c.x + d3 * d4.x;
        ay += d0 * a.y + d1 * b.y + d2 * c.y + d3 * d4.y;
        az += d0 * a.z + d1 * b.z + d2 * c.z + d3 * d4.z;
        aw += d0 * a.w + d1 * b.w + d2 * c.w + d3 * d4.w;
    }
    for (; i < e; i++) {
        int s0 = g_csr[i];
        float d0 = g_dinv[s0];
        float4 a = Z[(size_t)s0 * 32 + q];
        ax += d0 * a.x; ay += d0 * a.y; az += d0 * a.z; aw += d0 * a.w;
    }
    float4 r = make_float4(dd * ax, dd * ay, dd * az, dd * aw);
    ((float4*)part[nl])[q] = r;
    if (q == 0) sg[nl] = bat[node];
    __syncthreads();

    bool uniform = true;
    const int g0 = sg[0];
#pragma unroll
    for (int t = 1; t < 8; t++) uniform &= (sg[t] == g0);

    if (uniform) {
        if (threadIdx.x < 32) {
            float4 sum = make_float4(0.f, 0.f, 0.f, 0.f);
#pragma unroll
            for (int t = 0; t < 8; t++) {
                float4 v = ((float4*)part[t])[threadIdx.x];
                sum.x += v.x; sum.y += v.y; sum.z += v.z; sum.w += v.w;
            }
            redv4(g_S + g0 * HH + threadIdx.x * 4, sum);
        }
    } else {
        redv4(g_S + sg[nl] * HH + q * 4, r);   // rare boundary blocks
    }
}

// ---------------------------------------------------------------------------
// FFMA2 GEMM (proven R9 config): Z[N,128] = relu(A[N,K] @ W[K,128] + b).
template <int K>
__global__ void __launch_bounds__(256) gemm_kernel(const float* __restrict__ A,
                                                   const float* __restrict__ W,
                                                   const float* __restrict__ bias,
                                                   float* __restrict__ Z) {
    constexpr int KP = K + 4;
    extern __shared__ char smraw[];
    float* Ash = (float*)smraw;                       // [64][KP]
    float2* Wsh = (float2*)(smraw + 64 * KP * 4);     // [128 cols][17 k-pairs]
    const int tid = threadIdx.x;
    const int lane = tid & 31;
    const int rg = tid >> 5;
    const int blockRow = blockIdx.x * 64;

#pragma unroll
    for (int f4 = tid; f4 < 64 * (K / 4); f4 += 256) {
        int row = f4 / (K / 4);
        int q = f4 % (K / 4);
        int grow = blockRow + row;
        float4 v = (grow < NN) ? *(const float4*)(A + (size_t)grow * K + q * 4)
                               : make_float4(0.f, 0.f, 0.f, 0.f);
        *(float4*)(Ash + row * KP + 4 * q) = v;
    }

    unsigned long long acc2[8][4];
#pragma unroll
    for (int i = 0; i < 8; i++)
#pragma unroll
        for (int j = 0; j < 4; j++) acc2[i][j] = 0ull;

    for (int kc = 0; kc < K; kc += 32) {
        __syncthreads();
        {
            int c = tid & 127;
            int half = tid >> 7;
#pragma unroll
            for (int t = 0; t < 8; t++) {
                int k2 = half * 8 + t;
                float w0 = W[(size_t)(kc + 2 * k2) * HH + c];
                float w1 = W[(size_t)(kc + 2 * k2 + 1) * HH + c];
                Wsh[c * 17 + k2] = make_float2(w0, w1);
            }
        }
        __syncthreads();
#pragma unroll
        for (int k2 = 0; k2 < 16; k2++) {
            unsigned long long a2[8], w2[4];
#pragma unroll
            for (int i = 0; i < 8; i++)
                a2[i] = *(const unsigned long long*)(Ash + (rg * 8 + i) * KP + kc + 2 * k2);
#pragma unroll
            for (int j = 0; j < 4; j++)
                w2[j] = *(const unsigned long long*)(&Wsh[(lane + 32 * j) * 17 + k2]);
#pragma unroll
            for (int i = 0; i < 8; i++)
#pragma unroll
                for (int j = 0; j < 4; j++) ffma2(acc2[i][j], a2[i], w2[j]);
        }
    }

    float b[4];
#pragma unroll
    for (int j = 0; j < 4; j++) b[j] = bias[lane + 32 * j];
#pragma unroll
    for (int i = 0; i < 8; i++) {
        int grow = blockRow + rg * 8 + i;
        if (grow >= NN) continue;
        float* Zr = Z + (size_t)grow * HH;
#pragma unroll
        for (int j = 0; j < 4; j++) {
            float o = fsum2(acc2[i][j]) + b[j];
            Zr[lane + 32 * j] = fmaxf(o, 0.f);
        }
    }
}

// ---------------------------------------------------------------------------
// MLP head. S comes presummed from agg3_pool; layer-3 GEMM folded by linearity:
//   p = (S @ W3)/cnt + b3.
__global__ void mlp_kernel(const int* __restrict__ bat,
                           const float* __restrict__ W3,
                           const float* __restrict__ b3,
                           const float* __restrict__ fw1, const float* __restrict__ fb1,
                           const float* __restrict__ fw2, const float* __restrict__ fb2,
                           float* __restrict__ out) {
    const int g = blockIdx.x;
    const int j = threadIdx.x;  // 128
    __shared__ int bounds[2];
    __shared__ __align__(16) float S[HH];
    __shared__ __align__(16) float p[HH];
    __shared__ __align__(16) float z[HH];

    if (j < 2) {
        int key = g + j;
        int lo = 0, hi = NN;
        while (lo < hi) {
            int mid = (lo + hi) >> 1;
            if (bat[mid] < key) lo = mid + 1;
            else hi = mid;
        }
        bounds[j] = lo;
    }
    S[j] = g_S[g * HH + j];
    __syncthreads();
    const int lo = bounds[0], hi = bounds[1];

    {
        float acc = 0.f;
#pragma unroll 8
        for (int k = 0; k < HH; k++) acc += S[k] * W3[k * HH + j];
        p[j] = (hi > lo) ? acc / (float)(hi - lo) + b3[j] : 0.0f;
    }
    __syncthreads();
    {
        float acc = fb1[j];
#pragma unroll 8
        for (int k = 0; k < HH; k++) acc += p[k] * fw1[k * HH + j];
        z[j] = fmaxf(acc, 0.0f);
    }
    __syncthreads();
    if (j < 4) {
        float o = fb2[j];
#pragma unroll 8
        for (int k = 0; k < HH; k++) o += z[k] * fw2[k * 4 + j];
        out[g * 4 + j] = o;
    }
}

// ---------------------------------------------------------------------------
extern "C" void kernel_launch(void* const* d_in, const int* in_sizes, int n_in,
                              void* d_out, int out_size) {
    const float* x   = (const float*)d_in[0];
    const float* W1  = (const float*)d_in[1];
    const float* b1  = (const float*)d_in[2];
    const float* W2  = (const float*)d_in[3];
    const float* b2  = (const float*)d_in[4];
    const float* W3  = (const float*)d_in[5];
    const float* b3  = (const float*)d_in[6];
    const float* fw1 = (const float*)d_in[7];
    const float* fb1 = (const float*)d_in[8];
    const float* fw2 = (const float*)d_in[9];
    const float* fb2 = (const float*)d_in[10];
    const int*   ei  = (const int*)d_in[11];
    const int*   bat = (const int*)d_in[12];
    float* out = (float*)d_out;

    float *du, *dz;
    cudaGetSymbolAddress((void**)&du, g_u);
    cudaGetSymbolAddress((void**)&dz, g_z);

    const int SMEM64 = 64 * (FIN + 4) * 4 + 128 * 17 * 8;   // 34816
    const int SMEM128 = 64 * (HH + 4) * 4 + 128 * 17 * 8;   // 51200
    cudaFuncSetAttribute(gemm_kernel<FIN>,
                         cudaFuncAttributeMaxDynamicSharedMemorySize, SMEM64);
    cudaFuncSetAttribute(gemm_kernel<HH>,
                         cudaFuncAttributeMaxDynamicSharedMemorySize, SMEM128);

    // --- CSR build (+ dinv) ---
    init_kernel<<<(NN + 255) / 256, 256>>>();
    hist_kernel<<<(EE + 255) / 256, 256>>>(ei);
    scan1_kernel<<<NBLK, 256>>>();
    scan3_kernel<<<(NN + 255) / 256, 256>>>();
    scatter_kernel<<<(EE + 255) / 256, 256>>>(ei);

    const int GEMM_GRID = (NN + 63) / 64;  // 1563

    // Layer 1
    agg_kernel<FIN><<<(NN * 16 + 255) / 256, 256>>>(x, du);
    gemm_kernel<FIN><<<GEMM_GRID, 256, SMEM64>>>(du, W1, b1, dz);
    // Layer 2
    agg_kernel<HH><<<(NN * 32 + 255) / 256, 256>>>(dz, du);
    gemm_kernel<HH><<<GEMM_GRID, 256, SMEM128>>>(du, W2, b2, dz);
    // Layer 3: aggregation fused with pooling (no u3 round-trip)
    agg3_pool_kernel<<<(NN * 32) / 256, 256>>>(dz, bat);

    mlp_kernel<<<GG, HH>>>(bat, W3, b3, fw1, fb1, fw2, fb2, out);
}

// round 16
// speedup vs baseline: 1.2310x; 1.0348x over previous
#include <cuda_runtime.h>
#include <cuda_fp16.h>
#include <cstdint>

#define NN 100000
#define EE 800000
#define GG 64
#define HH 128
#define FIN 64
#define NBLK ((NN + 1023) / 1024)   // 98

// Scratch (__device__ globals; no allocation allowed)
__device__ __align__(16) float g_u[(size_t)NN * HH];
__device__ __align__(16) __half g_zh[(size_t)NN * HH];   // fp16 activations
__device__ float g_dinv[NN];
__device__ int   g_cnt[NN];
__device__ int   g_off[NN + 1];
__device__ int   g_cur[NN];
__device__ int   g_csr[EE];
__device__ int   g_bsum[128];
__device__ __align__(16) float g_S[GG * HH];   // per-graph pooled sums

// ---------------------------------------------------------------------------
__device__ __forceinline__ void ffma2(unsigned long long& acc, unsigned long long a,
                                      unsigned long long b) {
    asm("fma.rn.f32x2 %0, %1, %2, %0;" : "+l"(acc) : "l"(a), "l"(b));
}
__device__ __forceinline__ float fsum2(unsigned long long v) {
    float lo, hi;
    asm("mov.b64 {%0,%1}, %2;" : "=f"(lo), "=f"(hi) : "l"(v));
    return lo + hi;
}
__device__ __forceinline__ void redv4(float* p, float4 v) {
    asm volatile("red.global.add.v4.f32 [%0], {%1, %2, %3, %4};" ::"l"(p),
                 "f"(v.x), "f"(v.y), "f"(v.z), "f"(v.w) : "memory");
}
// Load 4 consecutive fp16 values (8B) and widen to float4.
__device__ __forceinline__ float4 ld_h4(const uint2* base, size_t idx) {
    uint2 r = base[idx];
    half2 h0 = *reinterpret_cast<half2*>(&r.x);
    half2 h1 = *reinterpret_cast<half2*>(&r.y);
    float2 f0 = __half22float2(h0);
    float2 f1 = __half22float2(h1);
    return make_float4(f0.x, f0.y, f1.x, f1.y);
}

// ---------------------------------------------------------------------------
__global__ void init_kernel() {
    int i = blockIdx.x * blockDim.x + threadIdx.x;
    if (i < NN) g_cnt[i] = 0;
    if (i < GG * HH) g_S[i] = 0.0f;
}
__global__ void hist_kernel(const int* __restrict__ ei) {
    int e = blockIdx.x * blockDim.x + threadIdx.x;
    if (e < EE) atomicAdd(&g_cnt[ei[EE + e]], 1);
}

// Block scan (1024/block) + dinv
__global__ void scan1_kernel() {
    __shared__ int ssum[256];
    const int tid = threadIdx.x;
    const int base = blockIdx.x * 1024 + tid * 4;
    int v[4];
#pragma unroll
    for (int j = 0; j < 4; j++) {
        int idx = base + j;
        v[j] = (idx < NN) ? g_cnt[idx] : 0;
        if (idx < NN) g_dinv[idx] = rsqrtf((float)v[j] + 1.0f);
    }
    int s = v[0] + v[1] + v[2] + v[3];
    ssum[tid] = s;
    __syncthreads();
    for (int d = 1; d < 256; d <<= 1) {
        int t = (tid >= d) ? ssum[tid - d] : 0;
        __syncthreads();
        ssum[tid] += t;
        __syncthreads();
    }
    int run = ssum[tid] - s;
#pragma unroll
    for (int j = 0; j < 4; j++) {
        int idx = base + j;
        if (idx < NN) g_off[idx] = run;
        run += v[j];
    }
    if (tid == 255) g_bsum[blockIdx.x] = ssum[255];
}

// scan3: scan2 folded in (each block redundantly scans the 98 block sums).
__global__ void scan3_kernel() {
    __shared__ int pre[128];
    const int tid = threadIdx.x;  // 256
    int v = 0;
    if (tid < 128) {
        v = (tid < NBLK) ? g_bsum[tid] : 0;
        pre[tid] = v;
    }
    __syncthreads();
    for (int d = 1; d < 128; d <<= 1) {
        int t = 0;
        if (tid < 128 && tid >= d) t = pre[tid - d];
        __syncthreads();
        if (tid < 128) pre[tid] += t;
        __syncthreads();
    }
    if (tid < 128) pre[tid] -= v;  // exclusive
    __syncthreads();
    int i = blockIdx.x * 256 + tid;
    if (i < NN) {
        int off = g_off[i] + pre[i >> 10];
        g_off[i] = off;
        g_cur[i] = off;
    }
    if (i == 0) g_off[NN] = EE;
}
__global__ void scatter_kernel(const int* __restrict__ ei) {
    int e = blockIdx.x * blockDim.x + threadIdx.x;
    if (e >= EE) return;
    int pos = atomicAdd(&g_cur[ei[EE + e]], 1);
    g_csr[pos] = ei[e];
}

// ---------------------------------------------------------------------------
// Layer-1 aggregation: u = A_hat * x (fp32 input, 64-dim). Proven R15 version.
__global__ void agg1_kernel(const float* __restrict__ z, float* __restrict__ u) {
    constexpr int GPN = FIN / 4;   // 16
    const int gt = blockIdx.x * 256 + threadIdx.x;
    const int node = gt >> 4;
    if (node >= NN) return;
    const int q = gt & (GPN - 1);
    const float dd = g_dinv[node];
    const int s = g_off[node], e = g_off[node + 1];
    const float4* Z = (const float4*)z;
    float4 v0 = Z[(size_t)node * GPN + q];
    float ax = dd * v0.x, ay = dd * v0.y, az = dd * v0.z, aw = dd * v0.w;
    int i = s;
    for (; i + 4 <= e; i += 4) {
        int s0 = g_csr[i], s1 = g_csr[i + 1], s2 = g_csr[i + 2], s3 = g_csr[i + 3];
        float d0 = g_dinv[s0], d1 = g_dinv[s1], d2 = g_dinv[s2], d3 = g_dinv[s3];
        float4 a = Z[(size_t)s0 * GPN + q];
        float4 b = Z[(size_t)s1 * GPN + q];
        float4 c = Z[(size_t)s2 * GPN + q];
        float4 d4 = Z[(size_t)s3 * GPN + q];
        ax += d0 * a.x + d1 * b.x + d2 * c.x + d3 * d4.x;
        ay += d0 * a.y + d1 * b.y + d2 * c.y + d3 * d4.y;
        az += d0 * a.z + d1 * b.z + d2 * c.z + d3 * d4.z;
        aw += d0 * a.w + d1 * b.w + d2 * c.w + d3 * d4.w;
    }
    for (; i < e; i++) {
        int s0 = g_csr[i];
        float d0 = g_dinv[s0];
        float4 a = Z[(size_t)s0 * GPN + q];
        ax += d0 * a.x; ay += d0 * a.y; az += d0 * a.z; aw += d0 * a.w;
    }
    ((float4*)u)[(size_t)node * GPN + q] = make_float4(dd * ax, dd * ay, dd * az, dd * aw);
}

// 128-dim aggregation from fp16 z: u = A_hat * zh.
__global__ void agg_f16_kernel(const __half* __restrict__ zh, float* __restrict__ u) {
    const int gt = blockIdx.x * 256 + threadIdx.x;
    const int node = gt >> 5;
    if (node >= NN) return;
    const int q = gt & 31;
    const float dd = g_dinv[node];
    const int s = g_off[node], e = g_off[node + 1];
    const uint2* Z = (const uint2*)zh;   // 32 uint2 per row
    float4 v0 = ld_h4(Z, (size_t)node * 32 + q);
    float ax = dd * v0.x, ay = dd * v0.y, az = dd * v0.z, aw = dd * v0.w;
    int i = s;
    for (; i + 4 <= e; i += 4) {
        int s0 = g_csr[i], s1 = g_csr[i + 1], s2 = g_csr[i + 2], s3 = g_csr[i + 3];
        float d0 = g_dinv[s0], d1 = g_dinv[s1], d2 = g_dinv[s2], d3 = g_dinv[s3];
        float4 a = ld_h4(Z, (size_t)s0 * 32 + q);
        float4 b = ld_h4(Z, (size_t)s1 * 32 + q);
        float4 c = ld_h4(Z, (size_t)s2 * 32 + q);
        float4 d4 = ld_h4(Z, (size_t)s3 * 32 + q);
        ax += d0 * a.x + d1 * b.x + d2 * c.x + d3 * d4.x;
        ay += d0 * a.y + d1 * b.y + d2 * c.y + d3 * d4.y;
        az += d0 * a.z + d1 * b.z + d2 * c.z + d3 * d4.z;
        aw += d0 * a.w + d1 * b.w + d2 * c.w + d3 * d4.w;
    }
    for (; i < e; i++) {
        int s0 = g_csr[i];
        float d0 = g_dinv[s0];
        float4 a = ld_h4(Z, (size_t)s0 * 32 + q);
        ax += d0 * a.x; ay += d0 * a.y; az += d0 * a.z; aw += d0 * a.w;
    }
    ((float4*)u)[(size_t)node * 32 + q] = make_float4(dd * ax, dd * ay, dd * az, dd * aw);
}

// Layer-3 aggregation (fp16 z) fused with pooling into g_S.
__global__ void agg3_pool_kernel(const __half* __restrict__ zh,
                                 const int* __restrict__ bat) {
    __shared__ __align__(16) float part[8][HH];
    __shared__ int sg[8];
    const int gt = blockIdx.x * 256 + threadIdx.x;
    const int node = gt >> 5;            // exact: NN*32 == grid*256
    const int q = threadIdx.x & 31;
    const int nl = threadIdx.x >> 5;
    const float dd = g_dinv[node];
    const int s = g_off[node], e = g_off[node + 1];
    const uint2* Z = (const uint2*)zh;
    float4 v0 = ld_h4(Z, (size_t)node * 32 + q);
    float ax = dd * v0.x, ay = dd * v0.y, az = dd * v0.z, aw = dd * v0.w;
    int i = s;
    for (; i + 4 <= e; i += 4) {
        int s0 = g_csr[i], s1 = g_csr[i + 1], s2 = g_csr[i + 2], s3 = g_csr[i + 3];
        float d0 = g_dinv[s0], d1 = g_dinv[s1], d2 = g_dinv[s2], d3 = g_dinv[s3];
        float4 a = ld_h4(Z, (size_t)s0 * 32 + q);
        float4 b = ld_h4(Z, (size_t)s1 * 32 + q);
        float4 c = ld_h4(Z, (size_t)s2 * 32 + q);
        float4 d4 = ld_h4(Z, (size_t)s3 * 32 + q);
        ax += d0 * a.x + d1 * b.x + d2 * c.x + d3 * d4.x;
        ay += d0 * a.y + d1 * b.y + d2 * c.y + d3 * d4.y;
        az += d0 * a.z + d1 * b.z + d2 * c.z + d3 * d4.z;
        aw += d0 * a.w + d1 * b.w + d2 * c.w + d3 * d4.w;
    }
    for (; i < e; i++) {
        int s0 = g_csr[i];
        float d0 = g_dinv[s0];
        float4 a = ld_h4(Z, (size_t)s0 * 32 + q);
        ax += d0 * a.x; ay += d0 * a.y; az += d0 * a.z; aw += d0 * a.w;
    }
    float4 r = make_float4(dd * ax, dd * ay, dd * az, dd * aw);
    ((float4*)part[nl])[q] = r;
    if (q == 0) sg[nl] = bat[node];
    __syncthreads();

    bool uniform = true;
    const int g0 = sg[0];
#pragma unroll
    for (int t = 1; t < 8; t++) uniform &= (sg[t] == g0);

    if (uniform) {
        if (threadIdx.x < 32) {
            float4 sum = make_float4(0.f, 0.f, 0.f, 0.f);
#pragma unroll
            for (int t = 0; t < 8; t++) {
                float4 v = ((float4*)part[t])[threadIdx.x];
                sum.x += v.x; sum.y += v.y; sum.z += v.z; sum.w += v.w;
            }
            redv4(g_S + g0 * HH + threadIdx.x * 4, sum);
        }
    } else {
        redv4(g_S + sg[nl] * HH + q * 4, r);
    }
}

// ---------------------------------------------------------------------------
// FFMA2 GEMM, fp16 output: Zh[N,128] = fp16(relu(A[N,K] @ W[K,128] + b)).
// Compute identical to the proven R9 config; epilogue stages fp16 in smem
// (reusing the A region) and writes coalesced 16B.
template <int K>
__global__ void __launch_bounds__(256) gemm_kernel(const float* __restrict__ A,
                                                   const float* __restrict__ W,
                                                   const float* __restrict__ bias,
                                                   __half* __restrict__ Zh) {
    constexpr int KP = K + 4;
    extern __shared__ char smraw[];
    float* Ash = (float*)smraw;                       // [64][KP]
    float2* Wsh = (float2*)(smraw + 64 * KP * 4);     // [128 cols][17 k-pairs]
    const int tid = threadIdx.x;
    const int lane = tid & 31;
    const int rg = tid >> 5;
    const int blockRow = blockIdx.x * 64;

#pragma unroll
    for (int f4 = tid; f4 < 64 * (K / 4); f4 += 256) {
        int row = f4 / (K / 4);
        int q = f4 % (K / 4);
        int grow = blockRow + row;
        float4 v = (grow < NN) ? *(const float4*)(A + (size_t)grow * K + q * 4)
                               : make_float4(0.f, 0.f, 0.f, 0.f);
        *(float4*)(Ash + row * KP + 4 * q) = v;
    }

    unsigned long long acc2[8][4];
#pragma unroll
    for (int i = 0; i < 8; i++)
#pragma unroll
        for (int j = 0; j < 4; j++) acc2[i][j] = 0ull;

    for (int kc = 0; kc < K; kc += 32) {
        __syncthreads();
        {
            int c = tid & 127;
            int half_ = tid >> 7;
#pragma unroll
            for (int t = 0; t < 8; t++) {
                int k2 = half_ * 8 + t;
                float w0 = W[(size_t)(kc + 2 * k2) * HH + c];
                float w1 = W[(size_t)(kc + 2 * k2 + 1) * HH + c];
                Wsh[c * 17 + k2] = make_float2(w0, w1);
            }
        }
        __syncthreads();
#pragma unroll
        for (int k2 = 0; k2 < 16; k2++) {
            unsigned long long a2[8], w2[4];
#pragma unroll
            for (int i = 0; i < 8; i++)
                a2[i] = *(const unsigned long long*)(Ash + (rg * 8 + i) * KP + kc + 2 * k2);
#pragma unroll
            for (int j = 0; j < 4; j++)
                w2[j] = *(const unsigned long long*)(&Wsh[(lane + 32 * j) * 17 + k2]);
#pragma unroll
            for (int i = 0; i < 8; i++)
#pragma unroll
                for (int j = 0; j < 4; j++) ffma2(acc2[i][j], a2[i], w2[j]);
        }
    }

    float b[4];
#pragma unroll
    for (int j = 0; j < 4; j++) b[j] = bias[lane + 32 * j];

    __syncthreads();                       // all Ash reads done; reuse as fp16 stage
    __half* stage = (__half*)smraw;        // [64][128] fp16 = 16 KB (fits A region)
#pragma unroll
    for (int i = 0; i < 8; i++) {
#pragma unroll
        for (int j = 0; j < 4; j++) {
            float o = fsum2(acc2[i][j]) + b[j];
            stage[(rg * 8 + i) * HH + lane + 32 * j] = __float2half_rn(fmaxf(o, 0.f));
        }
    }
    __syncthreads();
    // Coalesced copy-out: 16 uint4 per row (256B).
#pragma unroll
    for (int t = tid; t < 64 * 16; t += 256) {
        int row = t >> 4;
        int grow = blockRow + row;
        if (grow < NN)
            ((uint4*)(Zh + (size_t)grow * HH))[t & 15] = ((const uint4*)stage)[t];
    }
}

// ---------------------------------------------------------------------------
// MLP head. S presummed; layer-3 GEMM folded: p = (S @ W3)/cnt + b3.
__global__ void mlp_kernel(const int* __restrict__ bat,
                           const float* __restrict__ W3,
                           const float* __restrict__ b3,
                           const float* __restrict__ fw1, const float* __restrict__ fb1,
                           const float* __restrict__ fw2, const float* __restrict__ fb2,
                           float* __restrict__ out) {
    const int g = blockIdx.x;
    const int j = threadIdx.x;  // 128
    __shared__ int bounds[2];
    __shared__ __align__(16) float S[HH];
    __shared__ __align__(16) float p[HH];
    __shared__ __align__(16) float z[HH];

    if (j < 2) {
        int key = g + j;
        int lo = 0, hi = NN;
        while (lo < hi) {
            int mid = (lo + hi) >> 1;
            if (bat[mid] < key) lo = mid + 1;
            else hi = mid;
        }
        bounds[j] = lo;
    }
    S[j] = g_S[g * HH + j];
    __syncthreads();
    const int lo = bounds[0], hi = bounds[1];

    {
        float acc = 0.f;
#pragma unroll 8
        for (int k = 0; k < HH; k++) acc += S[k] * W3[k * HH + j];
        p[j] = (hi > lo) ? acc / (float)(hi - lo) + b3[j] : 0.0f;
    }
    __syncthreads();
    {
        float acc = fb1[j];
#pragma unroll 8
        for (int k = 0; k < HH; k++) acc += p[k] * fw1[k * HH + j];
        z[j] = fmaxf(acc, 0.0f);
    }
    __syncthreads();
    if (j < 4) {
        float o = fb2[j];
#pragma unroll 8
        for (int k = 0; k < HH; k++) o += z[k] * fw2[k * 4 + j];
        out[g * 4 + j] = o;
    }
}

// ---------------------------------------------------------------------------
extern "C" void kernel_launch(void* const* d_in, const int* in_sizes, int n_in,
                              void* d_out, int out_size) {
    const float* x   = (const float*)d_in[0];
    const float* W1  = (const float*)d_in[1];
    const float* b1  = (const float*)d_in[2];
    const float* W2  = (const float*)d_in[3];
    const float* b2  = (const float*)d_in[4];
    const float* W3  = (const float*)d_in[5];
    const float* b3  = (const float*)d_in[6];
    const float* fw1 = (const float*)d_in[7];
    const float* fb1 = (const float*)d_in[8];
    const float* fw2 = (const float*)d_in[9];
    const float* fb2 = (const float*)d_in[10];
    const int*   ei  = (const int*)d_in[11];
    const int*   bat = (const int*)d_in[12];
    float* out = (float*)d_out;

    float* du;
    __half* dzh;
    cudaGetSymbolAddress((void**)&du, g_u);
    cudaGetSymbolAddress((void**)&dzh, g_zh);

    const int SMEM64 = 64 * (FIN + 4) * 4 + 128 * 17 * 8;   // 34816
    const int SMEM128 = 64 * (HH + 4) * 4 + 128 * 17 * 8;   // 51200
    cudaFuncSetAttribute(gemm_kernel<FIN>,
                         cudaFuncAttributeMaxDynamicSharedMemorySize, SMEM64);
    cudaFuncSetAttribute(gemm_kernel<HH>,
                         cudaFuncAttributeMaxDynamicSharedMemorySize, SMEM128);

    // --- CSR build (+ dinv) ---
    init_kernel<<<(NN + 255) / 256, 256>>>();
    hist_kernel<<<(EE + 255) / 256, 256>>>(ei);
    scan1_kernel<<<NBLK, 256>>>();
    scan3_kernel<<<(NN + 255) / 256, 256>>>();
    scatter_kernel<<<(EE + 255) / 256, 256>>>(ei);

    const int GEMM_GRID = (NN + 63) / 64;  // 1563

    // Layer 1: u1 = A_hat x ; zh1 = fp16(relu(u1 W1 + b1))
    agg1_kernel<<<(NN * 16 + 255) / 256, 256>>>(x, du);
    gemm_kernel<FIN><<<GEMM_GRID, 256, SMEM64>>>(du, W1, b1, dzh);
    // Layer 2: u2 = A_hat zh1 ; zh2 = fp16(relu(u2 W2 + b2))
    agg_f16_kernel<<<(NN * 32 + 255) / 256, 256>>>(dzh, du);
    gemm_kernel<HH><<<GEMM_GRID, 256, SMEM128>>>(du, W2, b2, dzh);
    // Layer 3: aggregation fused with pooling (fp16 gather, no u3 round-trip)
    agg3_pool_kernel<<<(NN * 32) / 256, 256>>>(dzh, bat);

    mlp_kernel<<<GG, HH>>>(bat, W3, b3, fw1, fb1, fw2, fb2, out);
}

// round 17
// speedup vs baseline: 1.2424x; 1.0092x over previous
#include <cuda_runtime.h>
#include <cuda_fp16.h>
#include <cstdint>

#define NN 100000
#define EE 800000
#define GG 64
#define HH 128
#define FIN 64
#define NBLK ((NN + 1023) / 1024)   // 98

// Scratch (__device__ globals; no allocation allowed)
__device__ __align__(16) float g_u[(size_t)NN * HH];
__device__ __align__(16) __half g_zh[(size_t)NN * HH];   // fp16 activations
__device__ float g_dinv[NN];
__device__ int   g_cnt[NN];
__device__ int   g_off[NN + 1];
__device__ int   g_cur[NN];
__device__ int   g_csr[EE];
__device__ int   g_bsum[128];
__device__ __align__(16) float g_S[GG * HH];   // per-graph pooled sums

// ---------------------------------------------------------------------------
__device__ __forceinline__ void ffma2(unsigned long long& acc, unsigned long long a,
                                      unsigned long long b) {
    asm("fma.rn.f32x2 %0, %1, %2, %0;" : "+l"(acc) : "l"(a), "l"(b));
}
__device__ __forceinline__ float fsum2(unsigned long long v) {
    float lo, hi;
    asm("mov.b64 {%0,%1}, %2;" : "=f"(lo), "=f"(hi) : "l"(v));
    return lo + hi;
}
__device__ __forceinline__ void redv4(float* p, float4 v) {
    asm volatile("red.global.add.v4.f32 [%0], {%1, %2, %3, %4};" ::"l"(p),
                 "f"(v.x), "f"(v.y), "f"(v.z), "f"(v.w) : "memory");
}
__device__ __forceinline__ float4 h4_to_f4(uint2 r) {
    half2 h0 = *reinterpret_cast<half2*>(&r.x);
    half2 h1 = *reinterpret_cast<half2*>(&r.y);
    float2 f0 = __half22float2(h0);
    float2 f1 = __half22float2(h1);
    return make_float4(f0.x, f0.y, f1.x, f1.y);
}

// ---------------------------------------------------------------------------
__global__ void init_kernel() {
    int i = blockIdx.x * blockDim.x + threadIdx.x;
    if (i < NN) g_cnt[i] = 0;
    if (i < GG * HH) g_S[i] = 0.0f;
}
__global__ void hist_kernel(const int* __restrict__ ei) {
    int e = blockIdx.x * blockDim.x + threadIdx.x;
    if (e < EE) atomicAdd(&g_cnt[ei[EE + e]], 1);
}

// Block scan (1024/block) + dinv
__global__ void scan1_kernel() {
    __shared__ int ssum[256];
    const int tid = threadIdx.x;
    const int base = blockIdx.x * 1024 + tid * 4;
    int v[4];
#pragma unroll
    for (int j = 0; j < 4; j++) {
        int idx = base + j;
        v[j] = (idx < NN) ? g_cnt[idx] : 0;
        if (idx < NN) g_dinv[idx] = rsqrtf((float)v[j] + 1.0f);
    }
    int s = v[0] + v[1] + v[2] + v[3];
    ssum[tid] = s;
    __syncthreads();
    for (int d = 1; d < 256; d <<= 1) {
        int t = (tid >= d) ? ssum[tid - d] : 0;
        __syncthreads();
        ssum[tid] += t;
        __syncthreads();
    }
    int run = ssum[tid] - s;
#pragma unroll
    for (int j = 0; j < 4; j++) {
        int idx = base + j;
        if (idx < NN) g_off[idx] = run;
        run += v[j];
    }
    if (tid == 255) g_bsum[blockIdx.x] = ssum[255];
}

// scan3: scan2 folded in (each block redundantly scans the 98 block sums).
__global__ void scan3_kernel() {
    __shared__ int pre[128];
    const int tid = threadIdx.x;  // 256
    int v = 0;
    if (tid < 128) {
        v = (tid < NBLK) ? g_bsum[tid] : 0;
        pre[tid] = v;
    }
    __syncthreads();
    for (int d = 1; d < 128; d <<= 1) {
        int t = 0;
        if (tid < 128 && tid >= d) t = pre[tid - d];
        __syncthreads();
        if (tid < 128) pre[tid] += t;
        __syncthreads();
    }
    if (tid < 128) pre[tid] -= v;  // exclusive
    __syncthreads();
    int i = blockIdx.x * 256 + tid;
    if (i < NN) {
        int off = g_off[i] + pre[i >> 10];
        g_off[i] = off;
        g_cur[i] = off;
    }
    if (i == 0) g_off[NN] = EE;
}
__global__ void scatter_kernel(const int* __restrict__ ei) {
    int e = blockIdx.x * blockDim.x + threadIdx.x;
    if (e >= EE) return;
    int pos = atomicAdd(&g_cur[ei[EE + e]], 1);
    g_csr[pos] = ei[e];
}

// ---------------------------------------------------------------------------
// Layer-1 aggregation: u = A_hat * x (fp32, 64-dim). Unroll-8 batched prefetch.
__global__ void agg1_kernel(const float* __restrict__ z, float* __restrict__ u) {
    constexpr int GPN = FIN / 4;   // 16
    const int gt = blockIdx.x * 256 + threadIdx.x;
    const int node = gt >> 4;
    if (node >= NN) return;
    const int q = gt & (GPN - 1);
    const float dd = g_dinv[node];
    const int s = g_off[node], e = g_off[node + 1];
    const float4* Z = (const float4*)z;
    float4 v0 = Z[(size_t)node * GPN + q];
    float ax = dd * v0.x, ay = dd * v0.y, az = dd * v0.z, aw = dd * v0.w;
    int i = s;
    for (; i + 8 <= e; i += 8) {
        int sx[8];
#pragma unroll
        for (int t = 0; t < 8; t++) sx[t] = g_csr[i + t];
        float dv[8];
#pragma unroll
        for (int t = 0; t < 8; t++) dv[t] = g_dinv[sx[t]];
        float4 rr[8];
#pragma unroll
        for (int t = 0; t < 8; t++) rr[t] = Z[(size_t)sx[t] * GPN + q];
#pragma unroll
        for (int t = 0; t < 8; t++) {
            ax += dv[t] * rr[t].x;
            ay += dv[t] * rr[t].y;
            az += dv[t] * rr[t].z;
            aw += dv[t] * rr[t].w;
        }
    }
    for (; i + 4 <= e; i += 4) {
        int s0 = g_csr[i], s1 = g_csr[i + 1], s2 = g_csr[i + 2], s3 = g_csr[i + 3];
        float d0 = g_dinv[s0], d1 = g_dinv[s1], d2 = g_dinv[s2], d3 = g_dinv[s3];
        float4 a = Z[(size_t)s0 * GPN + q];
        float4 b = Z[(size_t)s1 * GPN + q];
        float4 c = Z[(size_t)s2 * GPN + q];
        float4 d4 = Z[(size_t)s3 * GPN + q];
        ax += d0 * a.x + d1 * b.x + d2 * c.x + d3 * d4.x;
        ay += d0 * a.y + d1 * b.y + d2 * c.y + d3 * d4.y;
        az += d0 * a.z + d1 * b.z + d2 * c.z + d3 * d4.z;
        aw += d0 * a.w + d1 * b.w + d2 * c.w + d3 * d4.w;
    }
    for (; i < e; i++) {
        int s0 = g_csr[i];
        float d0 = g_dinv[s0];
        float4 a = Z[(size_t)s0 * GPN + q];
        ax += d0 * a.x; ay += d0 * a.y; az += d0 * a.z; aw += d0 * a.w;
    }
    ((float4*)u)[(size_t)node * GPN + q] = make_float4(dd * ax, dd * ay, dd * az, dd * aw);
}

// 128-dim aggregation from fp16 z. Unroll-8 with raw uint2 batching.
__global__ void agg_f16_kernel(const __half* __restrict__ zh, float* __restrict__ u) {
    const int gt = blockIdx.x * 256 + threadIdx.x;
    const int node = gt >> 5;
    if (node >= NN) return;
    const int q = gt & 31;
    const float dd = g_dinv[node];
    const int s = g_off[node], e = g_off[node + 1];
    const uint2* Z = (const uint2*)zh;   // 32 uint2 per row
    float4 v0 = h4_to_f4(Z[(size_t)node * 32 + q]);
    float ax = dd * v0.x, ay = dd * v0.y, az = dd * v0.z, aw = dd * v0.w;
    int i = s;
    for (; i + 8 <= e; i += 8) {
        int sx[8];
#pragma unroll
        for (int t = 0; t < 8; t++) sx[t] = g_csr[i + t];
        float dv[8];
#pragma unroll
        for (int t = 0; t < 8; t++) dv[t] = g_dinv[sx[t]];
        uint2 rr[8];
#pragma unroll
        for (int t = 0; t < 8; t++) rr[t] = Z[(size_t)sx[t] * 32 + q];
#pragma unroll
        for (int t = 0; t < 8; t++) {
            float4 a = h4_to_f4(rr[t]);
            ax += dv[t] * a.x;
            ay += dv[t] * a.y;
            az += dv[t] * a.z;
            aw += dv[t] * a.w;
        }
    }
    for (; i + 4 <= e; i += 4) {
        int s0 = g_csr[i], s1 = g_csr[i + 1], s2 = g_csr[i + 2], s3 = g_csr[i + 3];
        float d0 = g_dinv[s0], d1 = g_dinv[s1], d2 = g_dinv[s2], d3 = g_dinv[s3];
        float4 a = h4_to_f4(Z[(size_t)s0 * 32 + q]);
        float4 b = h4_to_f4(Z[(size_t)s1 * 32 + q]);
        float4 c = h4_to_f4(Z[(size_t)s2 * 32 + q]);
        float4 d4 = h4_to_f4(Z[(size_t)s3 * 32 + q]);
        ax += d0 * a.x + d1 * b.x + d2 * c.x + d3 * d4.x;
        ay += d0 * a.y + d1 * b.y + d2 * c.y + d3 * d4.y;
        az += d0 * a.z + d1 * b.z + d2 * c.z + d3 * d4.z;
        aw += d0 * a.w + d1 * b.w + d2 * c.w + d3 * d4.w;
    }
    for (; i < e; i++) {
        int s0 = g_csr[i];
        float d0 = g_dinv[s0];
        float4 a = h4_to_f4(Z[(size_t)s0 * 32 + q]);
        ax += d0 * a.x; ay += d0 * a.y; az += d0 * a.z; aw += d0 * a.w;
    }
    ((float4*)u)[(size_t)node * 32 + q] = make_float4(dd * ax, dd * ay, dd * az, dd * aw);
}

// Layer-3 aggregation (fp16 z) fused with pooling into g_S. Unroll-8.
__global__ void agg3_pool_kernel(const __half* __restrict__ zh,
                                 const int* __restrict__ bat) {
    __shared__ __align__(16) float part[8][HH];
    __shared__ int sg[8];
    const int gt = blockIdx.x * 256 + threadIdx.x;
    const int node = gt >> 5;            // exact: NN*32 == grid*256
    const int q = threadIdx.x & 31;
    const int nl = threadIdx.x >> 5;
    const float dd = g_dinv[node];
    const int s = g_off[node], e = g_off[node + 1];
    const uint2* Z = (const uint2*)zh;
    float4 v0 = h4_to_f4(Z[(size_t)node * 32 + q]);
    float ax = dd * v0.x, ay = dd * v0.y, az = dd * v0.z, aw = dd * v0.w;
    int i = s;
    for (; i + 8 <= e; i += 8) {
        int sx[8];
#pragma unroll
        for (int t = 0; t < 8; t++) sx[t] = g_csr[i + t];
        float dv[8];
#pragma unroll
        for (int t = 0; t < 8; t++) dv[t] = g_dinv[sx[t]];
        uint2 rr[8];
#pragma unroll
        for (int t = 0; t < 8; t++) rr[t] = Z[(size_t)sx[t] * 32 + q];
#pragma unroll
        for (int t = 0; t < 8; t++) {
            float4 a = h4_to_f4(rr[t]);
            ax += dv[t] * a.x;
            ay += dv[t] * a.y;
            az += dv[t] * a.z;
            aw += dv[t] * a.w;
        }
    }
    for (; i + 4 <= e; i += 4) {
        int s0 = g_csr[i], s1 = g_csr[i + 1], s2 = g_csr[i + 2], s3 = g_csr[i + 3];
        float d0 = g_dinv[s0], d1 = g_dinv[s1], d2 = g_dinv[s2], d3 = g_dinv[s3];
        float4 a = h4_to_f4(Z[(size_t)s0 * 32 + q]);
        float4 b = h4_to_f4(Z[(size_t)s1 * 32 + q]);
        float4 c = h4_to_f4(Z[(size_t)s2 * 32 + q]);
        float4 d4 = h4_to_f4(Z[(size_t)s3 * 32 + q]);
        ax += d0 * a.x + d1 * b.x + d2 * c.x + d3 * d4.x;
        ay += d0 * a.y + d1 * b.y + d2 * c.y + d3 * d4.y;
        az += d0 * a.z + d1 * b.z + d2 * c.z + d3 * d4.z;
        aw += d0 * a.w + d1 * b.w + d2 * c.w + d3 * d4.w;
    }
    for (; i < e; i++) {
        int s0 = g_csr[i];
        float d0 = g_dinv[s0];
        float4 a = h4_to_f4(Z[(size_t)s0 * 32 + q]);
        ax += d0 * a.x; ay += d0 * a.y; az += d0 * a.z; aw += d0 * a.w;
    }
    float4 r = make_float4(dd * ax, dd * ay, dd * az, dd * aw);
    ((float4*)part[nl])[q] = r;
    if (q == 0) sg[nl] = bat[node];
    __syncthreads();

    bool uniform = true;
    const int g0 = sg[0];
#pragma unroll
    for (int t = 1; t < 8; t++) uniform &= (sg[t] == g0);

    if (uniform) {
        if (threadIdx.x < 32) {
            float4 sum = make_float4(0.f, 0.f, 0.f, 0.f);
#pragma unroll
            for (int t = 0; t < 8; t++) {
                float4 v = ((float4*)part[t])[threadIdx.x];
                sum.x += v.x; sum.y += v.y; sum.z += v.z; sum.w += v.w;
            }
            redv4(g_S + g0 * HH + threadIdx.x * 4, sum);
        }
    } else {
        redv4(g_S + sg[nl] * HH + q * 4, r);
    }
}

// ---------------------------------------------------------------------------
// FFMA2 GEMM, fp16 output: Zh[N,128] = fp16(relu(A[N,K] @ W[K,128] + b)).
template <int K>
__global__ void __launch_bounds__(256) gemm_kernel(const float* __restrict__ A,
                                                   const float* __restrict__ W,
                                                   const float* __restrict__ bias,
                                                   __half* __restrict__ Zh) {
    constexpr int KP = K + 4;
    extern __shared__ char smraw[];
    float* Ash = (float*)smraw;                       // [64][KP]
    float2* Wsh = (float2*)(smraw + 64 * KP * 4);     // [128 cols][17 k-pairs]
    const int tid = threadIdx.x;
    const int lane = tid & 31;
    const int rg = tid >> 5;
    const int blockRow = blockIdx.x * 64;

#pragma unroll
    for (int f4 = tid; f4 < 64 * (K / 4); f4 += 256) {
        int row = f4 / (K / 4);
        int q = f4 % (K / 4);
        int grow = blockRow + row;
        float4 v = (grow < NN) ? *(const float4*)(A + (size_t)grow * K + q * 4)
                               : make_float4(0.f, 0.f, 0.f, 0.f);
        *(float4*)(Ash + row * KP + 4 * q) = v;
    }

    unsigned long long acc2[8][4];
#pragma unroll
    for (int i = 0; i < 8; i++)
#pragma unroll
        for (int j = 0; j < 4; j++) acc2[i][j] = 0ull;

    for (int kc = 0; kc < K; kc += 32) {
        __syncthreads();
        {
            int c = tid & 127;
            int half_ = tid >> 7;
#pragma unroll
            for (int t = 0; t < 8; t++) {
                int k2 = half_ * 8 + t;
                float w0 = W[(size_t)(kc + 2 * k2) * HH + c];
                float w1 = W[(size_t)(kc + 2 * k2 + 1) * HH + c];
                Wsh[c * 17 + k2] = make_float2(w0, w1);
            }
        }
        __syncthreads();
#pragma unroll
        for (int k2 = 0; k2 < 16; k2++) {
            unsigned long long a2[8], w2[4];
#pragma unroll
            for (int i = 0; i < 8; i++)
                a2[i] = *(const unsigned long long*)(Ash + (rg * 8 + i) * KP + kc + 2 * k2);
#pragma unroll
            for (int j = 0; j < 4; j++)
                w2[j] = *(const unsigned long long*)(&Wsh[(lane + 32 * j) * 17 + k2]);
#pragma unroll
            for (int i = 0; i < 8; i++)
#pragma unroll
                for (int j = 0; j < 4; j++) ffma2(acc2[i][j], a2[i], w2[j]);
        }
    }

    float b[4];
#pragma unroll
    for (int j = 0; j < 4; j++) b[j] = bias[lane + 32 * j];

    __syncthreads();                       // all Ash reads done; reuse as fp16 stage
    __half* stage = (__half*)smraw;        // [64][128] fp16 = 16 KB
#pragma unroll
    for (int i = 0; i < 8; i++) {
#pragma unroll
        for (int j = 0; j < 4; j++) {
            float o = fsum2(acc2[i][j]) + b[j];
            stage[(rg * 8 + i) * HH + lane + 32 * j] = __float2half_rn(fmaxf(o, 0.f));
        }
    }
    __syncthreads();
#pragma unroll
    for (int t = tid; t < 64 * 16; t += 256) {
        int row = t >> 4;
        int grow = blockRow + row;
        if (grow < NN)
            ((uint4*)(Zh + (size_t)grow * HH))[t & 15] = ((const uint4*)stage)[t];
    }
}

// ---------------------------------------------------------------------------
// MLP head. S presummed; layer-3 GEMM folded: p = (S @ W3)/cnt + b3.
__global__ void mlp_kernel(const int* __restrict__ bat,
                           const float* __restrict__ W3,
                           const float* __restrict__ b3,
                           const float* __restrict__ fw1, const float* __restrict__ fb1,
                           const float* __restrict__ fw2, const float* __restrict__ fb2,
                           float* __restrict__ out) {
    const int g = blockIdx.x;
    const int j = threadIdx.x;  // 128
    __shared__ int bounds[2];
    __shared__ __align__(16) float S[HH];
    __shared__ __align__(16) float p[HH];
    __shared__ __align__(16) float z[HH];

    if (j < 2) {
        int key = g + j;
        int lo = 0, hi = NN;
        while (lo < hi) {
            int mid = (lo + hi) >> 1;
            if (bat[mid] < key) lo = mid + 1;
            else hi = mid;
        }
        bounds[j] = lo;
    }
    S[j] = g_S[g * HH + j];
    __syncthreads();
    const int lo = bounds[0], hi = bounds[1];

    {
        float acc = 0.f;
#pragma unroll 8
        for (int k = 0; k < HH; k++) acc += S[k] * W3[k * HH + j];
        p[j] = (hi > lo) ? acc / (float)(hi - lo) + b3[j] : 0.0f;
    }
    __syncthreads();
    {
        float acc = fb1[j];
#pragma unroll 8
        for (int k = 0; k < HH; k++) acc += p[k] * fw1[k * HH + j];
        z[j] = fmaxf(acc, 0.0f);
    }
    __syncthreads();
    if (j < 4) {
        float o = fb2[j];
#pragma unroll 8
        for (int k = 0; k < HH; k++) o += z[k] * fw2[k * 4 + j];
        out[g * 4 + j] = o;
    }
}

// ---------------------------------------------------------------------------
extern "C" void kernel_launch(void* const* d_in, const int* in_sizes, int n_in,
                              void* d_out, int out_size) {
    const float* x   = (const float*)d_in[0];
    const float* W1  = (const float*)d_in[1];
    const float* b1  = (const float*)d_in[2];
    const float* W2  = (const float*)d_in[3];
    const float* b2  = (const float*)d_in[4];
    const float* W3  = (const float*)d_in[5];
    const float* b3  = (const float*)d_in[6];
    const float* fw1 = (const float*)d_in[7];
    const float* fb1 = (const float*)d_in[8];
    const float* fw2 = (const float*)d_in[9];
    const float* fb2 = (const float*)d_in[10];
    const int*   ei  = (const int*)d_in[11];
    const int*   bat = (const int*)d_in[12];
    float* out = (float*)d_out;

    float* du;
    __half* dzh;
    cudaGetSymbolAddress((void**)&du, g_u);
    cudaGetSymbolAddress((void**)&dzh, g_zh);

    const int SMEM64 = 64 * (FIN + 4) * 4 + 128 * 17 * 8;   // 34816
    const int SMEM128 = 64 * (HH + 4) * 4 + 128 * 17 * 8;   // 51200
    cudaFuncSetAttribute(gemm_kernel<FIN>,
                         cudaFuncAttributeMaxDynamicSharedMemorySize, SMEM64);
    cudaFuncSetAttribute(gemm_kernel<HH>,
                         cudaFuncAttributeMaxDynamicSharedMemorySize, SMEM128);

    // --- CSR build (+ dinv) ---
    init_kernel<<<(NN + 255) / 256, 256>>>();
    hist_kernel<<<(EE + 255) / 256, 256>>>(ei);
    scan1_kernel<<<NBLK, 256>>>();
    scan3_kernel<<<(NN + 255) / 256, 256>>>();
    scatter_kernel<<<(EE + 255) / 256, 256>>>(ei);

    const int GEMM_GRID = (NN + 63) / 64;  // 1563

    // Layer 1: u1 = A_hat x ; zh1 = fp16(relu(u1 W1 + b1))
    agg1_kernel<<<(NN * 16 + 255) / 256, 256>>>(x, du);
    gemm_kernel<FIN><<<GEMM_GRID, 256, SMEM64>>>(du, W1, b1, dzh);
    // Layer 2: u2 = A_hat zh1 ; zh2 = fp16(relu(u2 W2 + b2))
    agg_f16_kernel<<<(NN * 32 + 255) / 256, 256>>>(dzh, du);
    gemm_kernel<HH><<<GEMM_GRID, 256, SMEM128>>>(du, W2, b2, dzh);
    // Layer 3: aggregation fused with pooling (fp16 gather, no u3 round-trip)
    agg3_pool_kernel<<<(NN * 32) / 256, 256>>>(dzh, bat);

    mlp_kernel<<<GG, HH>>>(bat, W3, b3, fw1, fb1, fw2, fb2, out);
}